// round 2
// baseline (speedup 1.0000x reference)
#include <cuda_runtime.h>
#include <cuda_bf16.h>
#include <mma.h>

using namespace nvcuda;

#define BATCH 8
#define CH    512
#define NPIX  4096
#define GROUPS 32
#define CPG   16
#define EPS   1e-6f

#define BCN (BATCH*CH*NPIX)   // 16777216 elements

// Scratch (static __device__ arrays: allocation-free per harness rules)
__device__ __nv_bfloat16 g_h[BCN];
__device__ __nv_bfloat16 g_q[BCN];
__device__ __nv_bfloat16 g_k[BCN];
__device__ __nv_bfloat16 g_v[BCN];
__device__ __nv_bfloat16 g_S[134217728];   // [B][N][N] logits -> probs (in-place)
__device__ __nv_bfloat16 g_o[BCN];

// ---------------------------------------------------------------------------
// GroupNorm: one block per (batch, group). Stats in fp32, output bf16.
// ---------------------------------------------------------------------------
__global__ __launch_bounds__(1024) void gn_kernel(const float* __restrict__ x,
                                                  const float* __restrict__ w,
                                                  const float* __restrict__ bgn) {
    int bg = blockIdx.x;                 // batch*32 + g
    size_t base = (size_t)bg * (CPG * NPIX);
    const float4* x4 = (const float4*)(x + base);
    int tid = threadIdx.x;

    float s = 0.f, ss = 0.f;
    #pragma unroll
    for (int t = 0; t < 16; t++) {
        float4 v = x4[tid + t * 1024];
        s  += v.x + v.y + v.z + v.w;
        ss += v.x * v.x + v.y * v.y + v.z * v.z + v.w * v.w;
    }
    __shared__ float rs[32], rss[32];
    #pragma unroll
    for (int o = 16; o; o >>= 1) {
        s  += __shfl_xor_sync(0xffffffffu, s, o);
        ss += __shfl_xor_sync(0xffffffffu, ss, o);
    }
    if ((tid & 31) == 0) { rs[tid >> 5] = s; rss[tid >> 5] = ss; }
    __syncthreads();
    if (tid < 32) {
        s = rs[tid]; ss = rss[tid];
        #pragma unroll
        for (int o = 16; o; o >>= 1) {
            s  += __shfl_xor_sync(0xffffffffu, s, o);
            ss += __shfl_xor_sync(0xffffffffu, ss, o);
        }
        if (tid == 0) {
            float mean = s * (1.f / 65536.f);
            float var  = ss * (1.f / 65536.f) - mean * mean;
            rs[0] = mean; rss[0] = rsqrtf(var + EPS);
        }
    }
    __syncthreads();
    float mean = rs[0], inv = rss[0];
    int c0 = (bg & 31) * CPG;

    uint2* h2 = (uint2*)(g_h + base);
    #pragma unroll
    for (int t = 0; t < 16; t++) {
        int i = tid + t * 1024;
        float4 v = x4[i];
        int c = c0 + (i >> 10);          // i*4/4096
        float sc  = w[c] * inv;
        float off = bgn[c] - mean * sc;
        __nv_bfloat162 lo = __floats2bfloat162_rn(v.x * sc + off, v.y * sc + off);
        __nv_bfloat162 hi = __floats2bfloat162_rn(v.z * sc + off, v.w * sc + off);
        uint2 u;
        u.x = *(unsigned int*)&lo;
        u.y = *(unsigned int*)&hi;
        h2[i] = u;
    }
}

// ---------------------------------------------------------------------------
// 1x1 conv GEMM: out[b,d,n] = sum_c W[d,c] * B[b,c,n] (+bias, scale / residual)
// DST: 0->g_q, 1->g_k, 2->g_v (input g_h, bf16 out); 3->proj (input g_o,
// fp32 out = X + result + bias).
// Tiles: BM=128 BN=128 BK=32, 8 warps (2x4), warp tile 64x32 (4x2 frags).
// ---------------------------------------------------------------------------
template<int DST>
__global__ __launch_bounds__(256) void conv1x1_kernel(const float* __restrict__ W,
                                                      const float* __restrict__ bias,
                                                      float scale,
                                                      const float* __restrict__ X,
                                                      float* __restrict__ OutF) {
    __shared__ __nv_bfloat16 As[128 * 48];     // row-major [m][k], ld=48
    __shared__ __nv_bfloat16 Bs[32 * 144];     // row-major [k][n], ld=144
    __shared__ float stage[8 * 256];

    int tid = threadIdx.x, warp = tid >> 5, lane = tid & 31;
    int wm = warp >> 2, wn = warp & 3;
    int m0 = blockIdx.y * 128, n0 = blockIdx.x * 128;
    const __nv_bfloat16* Bb = (DST == 3 ? g_o : g_h) + (size_t)blockIdx.z * CH * NPIX;

    wmma::fragment<wmma::accumulator, 16, 16, 16, float> acc[4][2];
    #pragma unroll
    for (int i = 0; i < 4; i++)
        #pragma unroll
        for (int j = 0; j < 2; j++) wmma::fill_fragment(acc[i][j], 0.f);

    for (int k0 = 0; k0 < CH; k0 += 32) {
        #pragma unroll
        for (int idx = tid; idx < 128 * 32; idx += 256) {
            int k = idx & 31, m = idx >> 5;
            As[m * 48 + k] = __float2bfloat16(W[(size_t)(m0 + m) * CH + k0 + k]);
        }
        #pragma unroll
        for (int idx = tid; idx < 32 * 128; idx += 256) {
            int n = idx & 127, kk = idx >> 7;
            Bs[kk * 144 + n] = Bb[(size_t)(k0 + kk) * NPIX + n0 + n];
        }
        __syncthreads();
        #pragma unroll
        for (int kk = 0; kk < 32; kk += 16) {
            wmma::fragment<wmma::matrix_a, 16, 16, 16, __nv_bfloat16, wmma::row_major> af[4];
            wmma::fragment<wmma::matrix_b, 16, 16, 16, __nv_bfloat16, wmma::row_major> bf[2];
            #pragma unroll
            for (int fm = 0; fm < 4; fm++)
                wmma::load_matrix_sync(af[fm], &As[(wm * 64 + fm * 16) * 48 + kk], 48);
            #pragma unroll
            for (int fn = 0; fn < 2; fn++)
                wmma::load_matrix_sync(bf[fn], &Bs[kk * 144 + wn * 32 + fn * 16], 144);
            #pragma unroll
            for (int fm = 0; fm < 4; fm++)
                #pragma unroll
                for (int fn = 0; fn < 2; fn++)
                    wmma::mma_sync(acc[fm][fn], af[fm], bf[fn], acc[fm][fn]);
        }
        __syncthreads();
    }

    float* st = stage + warp * 256;
    #pragma unroll
    for (int fm = 0; fm < 4; fm++)
        for (int fn = 0; fn < 2; fn++) {
            wmma::store_matrix_sync(st, acc[fm][fn], 16, wmma::mem_row_major);
            __syncwarp();
            int mb = m0 + wm * 64 + fm * 16, nb = n0 + wn * 32 + fn * 16;
            for (int e = lane; e < 256; e += 32) {
                int r = e >> 4, c2 = e & 15;
                int d = mb + r;
                size_t off = (size_t)blockIdx.z * CH * NPIX + (size_t)d * NPIX + nb + c2;
                float v = st[e] + bias[d];
                if (DST == 3) {
                    OutF[off] = X[off] + v;
                } else {
                    __nv_bfloat16* O = (DST == 0 ? g_q : DST == 1 ? g_k : g_v);
                    O[off] = __float2bfloat16(v * scale);
                }
            }
            __syncwarp();
        }
}

// ---------------------------------------------------------------------------
// S[b,i,j] = sum_c q[b,c,i]*k[b,c,j]  (scale pre-folded into q). A is q^T
// (col-major view of [c,i] storage), B is k row-major. Output bf16 logits.
// ---------------------------------------------------------------------------
__global__ __launch_bounds__(256) void attn_s_kernel() {
    __shared__ __nv_bfloat16 As[32 * 144];   // col-major: (m,k) at [k*144+m]
    __shared__ __nv_bfloat16 Bs[32 * 144];   // row-major: (k,n) at [k*144+n]
    __shared__ float stage[8 * 256];

    int tid = threadIdx.x, warp = tid >> 5, lane = tid & 31;
    int wm = warp >> 2, wn = warp & 3;
    int i0 = blockIdx.y * 128, j0 = blockIdx.x * 128;
    const __nv_bfloat16* Qb = g_q + (size_t)blockIdx.z * CH * NPIX;
    const __nv_bfloat16* Kb = g_k + (size_t)blockIdx.z * CH * NPIX;

    wmma::fragment<wmma::accumulator, 16, 16, 16, float> acc[4][2];
    #pragma unroll
    for (int i = 0; i < 4; i++)
        #pragma unroll
        for (int j = 0; j < 2; j++) wmma::fill_fragment(acc[i][j], 0.f);

    for (int k0 = 0; k0 < CH; k0 += 32) {
        #pragma unroll
        for (int idx = tid; idx < 32 * 128; idx += 256) {
            int m = idx & 127, kk = idx >> 7;
            As[kk * 144 + m] = Qb[(size_t)(k0 + kk) * NPIX + i0 + m];
        }
        #pragma unroll
        for (int idx = tid; idx < 32 * 128; idx += 256) {
            int n = idx & 127, kk = idx >> 7;
            Bs[kk * 144 + n] = Kb[(size_t)(k0 + kk) * NPIX + j0 + n];
        }
        __syncthreads();
        #pragma unroll
        for (int kk = 0; kk < 32; kk += 16) {
            wmma::fragment<wmma::matrix_a, 16, 16, 16, __nv_bfloat16, wmma::col_major> af[4];
            wmma::fragment<wmma::matrix_b, 16, 16, 16, __nv_bfloat16, wmma::row_major> bf[2];
            #pragma unroll
            for (int fm = 0; fm < 4; fm++)
                wmma::load_matrix_sync(af[fm], &As[kk * 144 + wm * 64 + fm * 16], 144);
            #pragma unroll
            for (int fn = 0; fn < 2; fn++)
                wmma::load_matrix_sync(bf[fn], &Bs[kk * 144 + wn * 32 + fn * 16], 144);
            #pragma unroll
            for (int fm = 0; fm < 4; fm++)
                #pragma unroll
                for (int fn = 0; fn < 2; fn++)
                    wmma::mma_sync(acc[fm][fn], af[fm], bf[fn], acc[fm][fn]);
        }
        __syncthreads();
    }

    float* st = stage + warp * 256;
    size_t Sb = (size_t)blockIdx.z * NPIX * NPIX;
    #pragma unroll
    for (int fm = 0; fm < 4; fm++)
        for (int fn = 0; fn < 2; fn++) {
            wmma::store_matrix_sync(st, acc[fm][fn], 16, wmma::mem_row_major);
            __syncwarp();
            int ib = i0 + wm * 64 + fm * 16, jb = j0 + wn * 32 + fn * 16;
            for (int e = lane; e < 256; e += 32) {
                int r = e >> 4, c2 = e & 15;
                g_S[Sb + (size_t)(ib + r) * NPIX + jb + c2] = __float2bfloat16(st[e]);
            }
            __syncwarp();
        }
}

// ---------------------------------------------------------------------------
// Row softmax over g_S, in place. One block per (b, i) row of 4096.
// ---------------------------------------------------------------------------
__global__ __launch_bounds__(256) void softmax_kernel() {
    size_t row = blockIdx.x;
    unsigned int* p2 = (unsigned int*)(g_S + row * NPIX);
    int tid = threadIdx.x;

    float vals[16];
    float m = -1e30f;
    #pragma unroll
    for (int t = 0; t < 8; t++) {
        unsigned int u = p2[tid + t * 256];
        __nv_bfloat162 b2 = *(__nv_bfloat162*)&u;
        vals[2 * t]     = __bfloat162float(b2.x);
        vals[2 * t + 1] = __bfloat162float(b2.y);
        m = fmaxf(m, fmaxf(vals[2 * t], vals[2 * t + 1]));
    }
    __shared__ float red[8];
    #pragma unroll
    for (int o = 16; o; o >>= 1) m = fmaxf(m, __shfl_xor_sync(0xffffffffu, m, o));
    if ((tid & 31) == 0) red[tid >> 5] = m;
    __syncthreads();
    float mm = red[0];
    #pragma unroll
    for (int w = 1; w < 8; w++) mm = fmaxf(mm, red[w]);

    float s = 0.f;
    #pragma unroll
    for (int t = 0; t < 16; t++) { vals[t] = __expf(vals[t] - mm); s += vals[t]; }
    #pragma unroll
    for (int o = 16; o; o >>= 1) s += __shfl_xor_sync(0xffffffffu, s, o);
    __syncthreads();
    if ((tid & 31) == 0) red[tid >> 5] = s;
    __syncthreads();
    float tot = 0.f;
    #pragma unroll
    for (int w = 0; w < 8; w++) tot += red[w];
    float inv = 1.f / tot;

    #pragma unroll
    for (int t = 0; t < 8; t++) {
        __nv_bfloat162 b2 = __floats2bfloat162_rn(vals[2 * t] * inv, vals[2 * t + 1] * inv);
        p2[tid + t * 256] = *(unsigned int*)&b2;
    }
}

// ---------------------------------------------------------------------------
// O[b,c,i] = sum_j v[b,c,j] * P[b,i,j].  A = v row-major [c,j];
// B = P^T (col-major view of [i][j] storage). K = 4096.
// ---------------------------------------------------------------------------
__global__ __launch_bounds__(256) void attn_o_kernel() {
    __shared__ __nv_bfloat16 As[128 * 48];   // row-major (m,k) at [m*48+k]
    __shared__ __nv_bfloat16 Bs[128 * 48];   // col-major (k,n) at [n*48+k]
    __shared__ float stage[8 * 256];

    int tid = threadIdx.x, warp = tid >> 5, lane = tid & 31;
    int wm = warp >> 2, wn = warp & 3;
    int m0 = blockIdx.y * 128;               // c tile
    int n0 = blockIdx.x * 128;               // i tile
    const __nv_bfloat16* Vb = g_v + (size_t)blockIdx.z * CH * NPIX;
    const __nv_bfloat16* Pb = g_S + (size_t)blockIdx.z * NPIX * NPIX;

    wmma::fragment<wmma::accumulator, 16, 16, 16, float> acc[4][2];
    #pragma unroll
    for (int i = 0; i < 4; i++)
        #pragma unroll
        for (int j = 0; j < 2; j++) wmma::fill_fragment(acc[i][j], 0.f);

    for (int k0 = 0; k0 < NPIX; k0 += 32) {
        #pragma unroll
        for (int idx = tid; idx < 128 * 32; idx += 256) {
            int k = idx & 31, m = idx >> 5;
            As[m * 48 + k] = Vb[(size_t)(m0 + m) * NPIX + k0 + k];
        }
        #pragma unroll
        for (int idx = tid; idx < 128 * 32; idx += 256) {
            int k = idx & 31, n = idx >> 5;
            Bs[n * 48 + k] = Pb[(size_t)(n0 + n) * NPIX + k0 + k];
        }
        __syncthreads();
        #pragma unroll
        for (int kk = 0; kk < 32; kk += 16) {
            wmma::fragment<wmma::matrix_a, 16, 16, 16, __nv_bfloat16, wmma::row_major> af[4];
            wmma::fragment<wmma::matrix_b, 16, 16, 16, __nv_bfloat16, wmma::col_major> bf[2];
            #pragma unroll
            for (int fm = 0; fm < 4; fm++)
                wmma::load_matrix_sync(af[fm], &As[(wm * 64 + fm * 16) * 48 + kk], 48);
            #pragma unroll
            for (int fn = 0; fn < 2; fn++)
                wmma::load_matrix_sync(bf[fn], &Bs[(wn * 32 + fn * 16) * 48 + kk], 48);
            #pragma unroll
            for (int fm = 0; fm < 4; fm++)
                #pragma unroll
                for (int fn = 0; fn < 2; fn++)
                    wmma::mma_sync(acc[fm][fn], af[fm], bf[fn], acc[fm][fn]);
        }
        __syncthreads();
    }

    float* st = stage + warp * 256;
    #pragma unroll
    for (int fm = 0; fm < 4; fm++)
        for (int fn = 0; fn < 2; fn++) {
            wmma::store_matrix_sync(st, acc[fm][fn], 16, wmma::mem_row_major);
            __syncwarp();
            int mb = m0 + wm * 64 + fm * 16, nb = n0 + wn * 32 + fn * 16;
            for (int e = lane; e < 256; e += 32) {
                int r = e >> 4, c2 = e & 15;
                g_o[(size_t)blockIdx.z * CH * NPIX + (size_t)(mb + r) * NPIX + nb + c2] =
                    __float2bfloat16(st[e]);
            }
            __syncwarp();
        }
}

// ---------------------------------------------------------------------------
extern "C" void kernel_launch(void* const* d_in, const int* in_sizes, int n_in,
                              void* d_out, int out_size) {
    (void)in_sizes; (void)n_in; (void)out_size;
    const float* x    = (const float*)d_in[0];
    const float* gn_w = (const float*)d_in[1];
    const float* gn_b = (const float*)d_in[2];
    const float* q_w  = (const float*)d_in[3];
    const float* q_b  = (const float*)d_in[4];
    const float* k_w  = (const float*)d_in[5];
    const float* k_b  = (const float*)d_in[6];
    const float* v_w  = (const float*)d_in[7];
    const float* v_b  = (const float*)d_in[8];
    const float* p_w  = (const float*)d_in[9];
    const float* p_b  = (const float*)d_in[10];
    float* out = (float*)d_out;

    const float qscale = 0.044194173824159216f;  // 512^-0.5

    gn_kernel<<<BATCH * GROUPS, 1024>>>(x, gn_w, gn_b);

    dim3 gc(NPIX / 128, CH / 128, BATCH);        // (32, 4, 8)
    conv1x1_kernel<0><<<gc, 256>>>(q_w, q_b, qscale, nullptr, nullptr);
    conv1x1_kernel<1><<<gc, 256>>>(k_w, k_b, 1.0f, nullptr, nullptr);
    conv1x1_kernel<2><<<gc, 256>>>(v_w, v_b, 1.0f, nullptr, nullptr);

    attn_s_kernel<<<dim3(NPIX / 128, NPIX / 128, BATCH), 256>>>();
    softmax_kernel<<<BATCH * NPIX, 256>>>();
    attn_o_kernel<<<gc, 256>>>();

    conv1x1_kernel<3><<<gc, 256>>>(p_w, p_b, 1.0f, x, out);
}

// round 4
// speedup vs baseline: 5.0187x; 5.0187x over previous
#include <cuda_runtime.h>
#include <cuda_bf16.h>
#include <cstdint>

#define BATCH 8
#define CH    512
#define NPIX  4096
#define EPS   1e-6f

// ---------------------------------------------------------------------------
// Scratch (__device__ globals: allocation-free per harness rules)
// ---------------------------------------------------------------------------
__device__ __nv_bfloat16 g_ht[BATCH * NPIX * CH];   // h transposed [b][n][c]
__device__ __nv_bfloat16 g_qt[BATCH * NPIX * CH];   // q_t [b][n][d]
__device__ __nv_bfloat16 g_kt[BATCH * NPIX * CH];   // k_t [b][n][d]
__device__ __nv_bfloat16 g_v [BATCH * CH * NPIX];   // v   [b][d][n]
__device__ __nv_bfloat16 g_ot[BATCH * NPIX * CH];   // o_t [b][n][c]
__device__ __nv_bfloat16 g_S [134217728];           // [b][i][j] logits -> probs
__device__ __nv_bfloat16 g_wq[CH * CH], g_wk[CH * CH], g_wv[CH * CH], g_wp[CH * CH];

// ---------------------------------------------------------------------------
// PTX helpers (base sm_80/sm_90 features only — PTX target here is sm_103
// WITHOUT the 'a' suffix, so no tcgen05/TMEM)
// ---------------------------------------------------------------------------
__device__ __forceinline__ uint32_t smem_u32(const void* p) {
    uint32_t a;
    asm("{ .reg .u64 t; cvta.to.shared.u64 t, %1; cvt.u32.u64 %0, t; }"
        : "=r"(a) : "l"(p));
    return a;
}
__device__ __forceinline__ void cp_async16(uint32_t saddr, const void* gptr) {
    asm volatile("cp.async.cg.shared.global [%0], [%1], 16;\n"
                 :: "r"(saddr), "l"(gptr));
}
#define CP_COMMIT() asm volatile("cp.async.commit_group;\n" ::: "memory")
#define CP_WAIT(N)  asm volatile("cp.async.wait_group %0;\n" :: "n"(N) : "memory")

__device__ __forceinline__ void ldsm4(uint32_t* r, uint32_t addr) {
    asm volatile("ldmatrix.sync.aligned.m8n8.x4.shared.b16 {%0,%1,%2,%3}, [%4];"
                 : "=r"(r[0]), "=r"(r[1]), "=r"(r[2]), "=r"(r[3]) : "r"(addr));
}
__device__ __forceinline__ void mma16816(float* c, const uint32_t* a,
                                         uint32_t b0, uint32_t b1) {
    asm volatile("mma.sync.aligned.m16n8k16.row.col.f32.bf16.bf16.f32 "
                 "{%0,%1,%2,%3}, {%4,%5,%6,%7}, {%8,%9}, {%0,%1,%2,%3};"
                 : "+f"(c[0]), "+f"(c[1]), "+f"(c[2]), "+f"(c[3])
                 : "r"(a[0]), "r"(a[1]), "r"(a[2]), "r"(a[3]), "r"(b0), "r"(b1));
}

// ---------------------------------------------------------------------------
// GroupNorm -> bf16, TRANSPOSED output g_ht[b][n][c]
// ---------------------------------------------------------------------------
__global__ __launch_bounds__(1024) void gn_kernel(const float* __restrict__ x,
                                                  const float* __restrict__ w,
                                                  const float* __restrict__ bgn) {
    int bg = blockIdx.x;                       // b*32 + g
    size_t base = (size_t)bg * (16 * NPIX);
    const float4* x4 = (const float4*)(x + base);
    int tid = threadIdx.x;

    float s = 0.f, ss = 0.f;
    #pragma unroll
    for (int t = 0; t < 16; t++) {
        float4 v = x4[tid + t * 1024];
        s  += v.x + v.y + v.z + v.w;
        ss += v.x * v.x + v.y * v.y + v.z * v.z + v.w * v.w;
    }
    __shared__ float rs[32], rss[32];
    __shared__ float sc_s[16], off_s[16];
    #pragma unroll
    for (int o = 16; o; o >>= 1) {
        s  += __shfl_xor_sync(0xffffffffu, s, o);
        ss += __shfl_xor_sync(0xffffffffu, ss, o);
    }
    if ((tid & 31) == 0) { rs[tid >> 5] = s; rss[tid >> 5] = ss; }
    __syncthreads();
    if (tid < 32) {
        s = rs[tid]; ss = rss[tid];
        #pragma unroll
        for (int o = 16; o; o >>= 1) {
            s  += __shfl_xor_sync(0xffffffffu, s, o);
            ss += __shfl_xor_sync(0xffffffffu, ss, o);
        }
        if (tid == 0) {
            float mean = s * (1.f / 65536.f);
            float var  = ss * (1.f / 65536.f) - mean * mean;
            rs[0] = mean; rss[0] = rsqrtf(var + EPS);
        }
    }
    __syncthreads();
    int b = bg >> 5, g = bg & 31, c0 = g * 16;
    if (tid < 16) {
        float mean = rs[0], inv = rss[0];
        float scv = w[c0 + tid] * inv;
        sc_s[tid]  = scv;
        off_s[tid] = bgn[c0 + tid] - mean * scv;
    }
    __syncthreads();

    #pragma unroll
    for (int nb = 0; nb < 4; nb++) {
        int n = nb * 1024 + tid;
        __nv_bfloat16 hv[16];
        #pragma unroll
        for (int cc = 0; cc < 16; cc++) {
            float xv = x[base + (size_t)cc * NPIX + n];
            hv[cc] = __float2bfloat16(xv * sc_s[cc] + off_s[cc]);
        }
        uint4* dst = (uint4*)(g_ht + ((size_t)b * NPIX + n) * CH + c0);
        uint4* src = (uint4*)hv;
        dst[0] = src[0];
        dst[1] = src[1];
    }
}

// ---------------------------------------------------------------------------
// Convert 4 weight matrices fp32 -> bf16
// ---------------------------------------------------------------------------
__global__ __launch_bounds__(256) void wconv_kernel(const float* __restrict__ q,
                                                    const float* __restrict__ k,
                                                    const float* __restrict__ v,
                                                    const float* __restrict__ p) {
    int i4 = blockIdx.x * 256 + threadIdx.x;   // float4 units
    const float* src = (i4 < 65536) ? q : (i4 < 131072) ? k : (i4 < 196608) ? v : p;
    __nv_bfloat16* dst = (i4 < 65536) ? g_wq : (i4 < 131072) ? g_wk : (i4 < 196608) ? g_wv : g_wp;
    int off = i4 & 65535;
    float4 vv = ((const float4*)src)[off];
    __nv_bfloat162 lo = __floats2bfloat162_rn(vv.x, vv.y);
    __nv_bfloat162 hi = __floats2bfloat162_rn(vv.z, vv.w);
    uint2 u; u.x = *(uint32_t*)&lo; u.y = *(uint32_t*)&hi;
    ((uint2*)dst)[off] = u;
}

// ---------------------------------------------------------------------------
// mma.sync bf16 GEMM: D[M x N] = sum_k A[m,k]*B[n,k], both K-major bf16.
// CTA tile 128x128, BK=64, 3-stage cp.async pipeline, swizzled smem,
// warp tile 64x32 (8 warps as 2x4), m16n8k16 fragments.
// EPI: 0 = bf16 (acc + bias[col]) * scale
//      1 = bf16  acc + bias[row]
//      2 = bf16  acc
//      3 = fp32  x + acc + bias[row]   (residual output)
// ---------------------------------------------------------------------------
template<int EPI>
__global__ void __launch_bounds__(256, 2) tc_gemm(
    const __nv_bfloat16* __restrict__ A, unsigned long long sA, int ldA,
    const __nv_bfloat16* __restrict__ B, unsigned long long sB, int ldB,
    void* __restrict__ C, unsigned long long sC, int ldC,
    const float* __restrict__ bias, float scale,
    const float* __restrict__ Xres, int K)
{
    extern __shared__ char dsm[];
    uint32_t sb = smem_u32(dsm);                 // 128B-aligned (dynamic smem)
    const uint32_t STG = 32768;                  // per-stage: A 16KB + B 16KB
    int tid = threadIdx.x, wid = tid >> 5, lane = tid & 31;
    int wm = wid >> 2, wn = wid & 3;

    const __nv_bfloat16* Ab = A + (size_t)blockIdx.z * sA + (size_t)blockIdx.y * 128 * ldA;
    const __nv_bfloat16* Bb = B + (size_t)blockIdx.z * sB + (size_t)blockIdx.x * 128 * ldB;

    // ldmatrix lane address components (swizzle: byte = row*128 + (kb ^ ((row&7)<<4)))
    int a_row = wm * 64 + (lane & 7) + ((lane >> 3) & 1) * 8;
    int a_kl  = (lane >> 4) * 16;
    uint32_t xr_a = (uint32_t)((a_row & 7) << 4);
    uint32_t a_off[4];
    #pragma unroll
    for (int i = 0; i < 4; i++) a_off[i] = (uint32_t)((a_row + i * 16) * 128);

    int b_row = wn * 32 + (lane & 7) + ((lane >> 4) << 3);
    int b_kl  = ((lane >> 3) & 1) * 16;
    uint32_t xr_b = (uint32_t)((b_row & 7) << 4);
    uint32_t b_off[2];
    #pragma unroll
    for (int p = 0; p < 2; p++) b_off[p] = (uint32_t)((b_row + p * 16) * 128);

    float acc[4][4][4];
    #pragma unroll
    for (int i = 0; i < 4; i++)
        #pragma unroll
        for (int j = 0; j < 4; j++)
            #pragma unroll
            for (int e = 0; e < 4; e++) acc[i][j][e] = 0.f;

    int nch = K >> 6;

    // stage loader: 1024 16B segs each for A and B, 256 threads -> 4+4 per thread
    auto load_stage = [&](int stg, int c) {
        uint32_t as = sb + (uint32_t)stg * STG;
        uint32_t bs = as + 16384;
        const __nv_bfloat16* ga = Ab + c * 64;
        const __nv_bfloat16* gb = Bb + c * 64;
        #pragma unroll
        for (int t = 0; t < 4; t++) {
            int sidx = t * 256 + tid;
            int m = sidx >> 3, cc = sidx & 7;
            uint32_t off = (uint32_t)(m * 128) + ((uint32_t)(cc * 16) ^ ((uint32_t)(m & 7) << 4));
            cp_async16(as + off, ga + (size_t)m * ldA + cc * 8);
            cp_async16(bs + off, gb + (size_t)m * ldB + cc * 8);
        }
    };

    if (0 < nch) { load_stage(0, 0); CP_COMMIT(); }
    if (1 < nch) { load_stage(1, 1); CP_COMMIT(); }

    for (int c = 0; c < nch; c++) {
        if (c + 2 < nch) { load_stage((c + 2) % 3, c + 2); CP_COMMIT(); }
        int remaining = nch - 1 - c;
        if (remaining >= 2)      { CP_WAIT(2); }
        else if (remaining == 1) { CP_WAIT(1); }
        else                     { CP_WAIT(0); }
        __syncthreads();

        uint32_t As = sb + (uint32_t)(c % 3) * STG;
        uint32_t Bs = As + 16384;
        #pragma unroll
        for (int k0 = 0; k0 < 64; k0 += 16) {
            uint32_t a[4][4], b[2][4];
            #pragma unroll
            for (int i = 0; i < 4; i++)
                ldsm4(a[i], As + a_off[i] + ((uint32_t)(k0 * 2 + a_kl) ^ xr_a));
            #pragma unroll
            for (int p = 0; p < 2; p++)
                ldsm4(b[p], Bs + b_off[p] + ((uint32_t)(k0 * 2 + b_kl) ^ xr_b));
            #pragma unroll
            for (int i = 0; i < 4; i++)
                #pragma unroll
                for (int j = 0; j < 4; j++)
                    mma16816(acc[i][j], a[i], b[j >> 1][(j & 1) * 2], b[j >> 1][(j & 1) * 2 + 1]);
        }
        __syncthreads();
    }

    // ---- epilogue: direct global stores ----
    int r0 = lane >> 2, cq = (lane & 3) * 2;
    #pragma unroll
    for (int i = 0; i < 4; i++) {
        int rowg0 = blockIdx.y * 128 + wm * 64 + i * 16 + r0;
        #pragma unroll
        for (int j = 0; j < 4; j++) {
            int colg = blockIdx.x * 128 + wn * 32 + j * 8 + cq;
            float v0 = acc[i][j][0], v1 = acc[i][j][1];
            float v2 = acc[i][j][2], v3 = acc[i][j][3];
            if (EPI == 0) {
                float b0 = bias[colg], b1 = bias[colg + 1];
                v0 = (v0 + b0) * scale; v1 = (v1 + b1) * scale;
                v2 = (v2 + b0) * scale; v3 = (v3 + b1) * scale;
            } else if (EPI == 1 || EPI == 3) {
                float bu = bias[rowg0], bl = bias[rowg0 + 8];
                v0 += bu; v1 += bu; v2 += bl; v3 += bl;
            }
            size_t o0 = (size_t)blockIdx.z * sC + (size_t)rowg0 * ldC + colg;
            size_t o1 = o0 + (size_t)8 * ldC;
            if (EPI == 3) {
                const float* Xr0 = Xres + o0;
                const float* Xr1 = Xres + o1;
                float2 f0; f0.x = Xr0[0] + v0; f0.y = Xr0[1] + v1;
                float2 f1; f1.x = Xr1[0] + v2; f1.y = Xr1[1] + v3;
                *(float2*)((float*)C + o0) = f0;
                *(float2*)((float*)C + o1) = f1;
            } else {
                __nv_bfloat162 p0 = __floats2bfloat162_rn(v0, v1);
                __nv_bfloat162 p1 = __floats2bfloat162_rn(v2, v3);
                *(__nv_bfloat162*)((__nv_bfloat16*)C + o0) = p0;
                *(__nv_bfloat162*)((__nv_bfloat16*)C + o1) = p1;
            }
        }
    }
}

// ---------------------------------------------------------------------------
// Row softmax over g_S, in place. One block per (b, i) row of 4096.
// ---------------------------------------------------------------------------
__global__ __launch_bounds__(256) void softmax_kernel() {
    size_t row = blockIdx.x;
    unsigned int* p2 = (unsigned int*)(g_S + row * NPIX);
    int tid = threadIdx.x;

    float vals[16];
    float m = -1e30f;
    #pragma unroll
    for (int t = 0; t < 8; t++) {
        unsigned int u = p2[tid + t * 256];
        __nv_bfloat162 b2 = *(__nv_bfloat162*)&u;
        vals[2 * t]     = __bfloat162float(b2.x);
        vals[2 * t + 1] = __bfloat162float(b2.y);
        m = fmaxf(m, fmaxf(vals[2 * t], vals[2 * t + 1]));
    }
    __shared__ float red[8];
    #pragma unroll
    for (int o = 16; o; o >>= 1) m = fmaxf(m, __shfl_xor_sync(0xffffffffu, m, o));
    if ((tid & 31) == 0) red[tid >> 5] = m;
    __syncthreads();
    float mm = red[0];
    #pragma unroll
    for (int w = 1; w < 8; w++) mm = fmaxf(mm, red[w]);

    float s = 0.f;
    #pragma unroll
    for (int t = 0; t < 16; t++) { vals[t] = __expf(vals[t] - mm); s += vals[t]; }
    #pragma unroll
    for (int o = 16; o; o >>= 1) s += __shfl_xor_sync(0xffffffffu, s, o);
    __syncthreads();
    if ((tid & 31) == 0) red[tid >> 5] = s;
    __syncthreads();
    float tot = 0.f;
    #pragma unroll
    for (int w = 0; w < 8; w++) tot += red[w];
    float inv = 1.f / tot;

    #pragma unroll
    for (int t = 0; t < 8; t++) {
        __nv_bfloat162 b2 = __floats2bfloat162_rn(vals[2 * t] * inv, vals[2 * t + 1] * inv);
        p2[tid + t * 256] = *(unsigned int*)&b2;
    }
}

// ---------------------------------------------------------------------------
extern "C" void kernel_launch(void* const* d_in, const int* in_sizes, int n_in,
                              void* d_out, int out_size) {
    (void)in_sizes; (void)n_in; (void)out_size;
    const float* x    = (const float*)d_in[0];
    const float* gn_w = (const float*)d_in[1];
    const float* gn_b = (const float*)d_in[2];
    const float* q_w  = (const float*)d_in[3];
    const float* q_b  = (const float*)d_in[4];
    const float* k_w  = (const float*)d_in[5];
    const float* k_b  = (const float*)d_in[6];
    const float* v_w  = (const float*)d_in[7];
    const float* v_b  = (const float*)d_in[8];
    const float* p_w  = (const float*)d_in[9];
    const float* p_b  = (const float*)d_in[10];
    float* out = (float*)d_out;

    const float qscale = 0.044194173824159216f;  // 512^-0.5
    const int SMEM = 98304;                      // 3 stages x 32KB
    static bool attr_done = false;
    if (!attr_done) {
        cudaFuncSetAttribute(tc_gemm<0>, cudaFuncAttributeMaxDynamicSharedMemorySize, SMEM);
        cudaFuncSetAttribute(tc_gemm<1>, cudaFuncAttributeMaxDynamicSharedMemorySize, SMEM);
        cudaFuncSetAttribute(tc_gemm<2>, cudaFuncAttributeMaxDynamicSharedMemorySize, SMEM);
        cudaFuncSetAttribute(tc_gemm<3>, cudaFuncAttributeMaxDynamicSharedMemorySize, SMEM);
        attr_done = true;
    }

    __nv_bfloat16 *ht, *qt, *kt, *vv, *ot, *Sp, *wq, *wk, *wv, *wp;
    cudaGetSymbolAddress((void**)&ht, g_ht);
    cudaGetSymbolAddress((void**)&qt, g_qt);
    cudaGetSymbolAddress((void**)&kt, g_kt);
    cudaGetSymbolAddress((void**)&vv, g_v);
    cudaGetSymbolAddress((void**)&ot, g_ot);
    cudaGetSymbolAddress((void**)&Sp, g_S);
    cudaGetSymbolAddress((void**)&wq, g_wq);
    cudaGetSymbolAddress((void**)&wk, g_wk);
    cudaGetSymbolAddress((void**)&wv, g_wv);
    cudaGetSymbolAddress((void**)&wp, g_wp);

    const unsigned long long sNC = (unsigned long long)NPIX * CH;    // 2097152
    const unsigned long long sNN = (unsigned long long)NPIX * NPIX;  // 16777216

    gn_kernel<<<BATCH * 32, 1024>>>(x, gn_w, gn_b);
    wconv_kernel<<<1024, 256>>>(q_w, k_w, v_w, p_w);

    // q_t[n][d] = (h_t . Wq^T + qb) * qscale : M=4096, N=512, K=512
    tc_gemm<0><<<dim3(4, 32, BATCH), 256, SMEM>>>(ht, sNC, CH, wq, 0ull, CH,
                                                  qt, sNC, CH, q_b, qscale, nullptr, CH);
    tc_gemm<0><<<dim3(4, 32, BATCH), 256, SMEM>>>(ht, sNC, CH, wk, 0ull, CH,
                                                  kt, sNC, CH, k_b, 1.0f, nullptr, CH);
    // v[d][n] = Wv . h_t^T + vb : M=512, N=4096, K=512
    tc_gemm<1><<<dim3(32, 4, BATCH), 256, SMEM>>>(wv, 0ull, CH, ht, sNC, CH,
                                                  vv, sNC, NPIX, v_b, 1.0f, nullptr, CH);
    // S[i][j] = q_t . k_t^T : M=4096, N=4096, K=512
    tc_gemm<2><<<dim3(32, 32, BATCH), 256, SMEM>>>(qt, sNC, CH, kt, sNC, CH,
                                                   Sp, sNN, NPIX, nullptr, 1.0f, nullptr, CH);
    softmax_kernel<<<BATCH * NPIX, 256>>>();
    // o_t[i][c] = P . v^T : M=4096, N=512, K=4096
    tc_gemm<2><<<dim3(4, 32, BATCH), 256, SMEM>>>(Sp, sNN, NPIX, vv, sNC, NPIX,
                                                  ot, sNC, CH, nullptr, 1.0f, nullptr, NPIX);
    // out[d][n] = x + Wp . o_t^T + pb : M=512, N=4096, K=512 (fp32 out)
    tc_gemm<3><<<dim3(32, 4, BATCH), 256, SMEM>>>(wp, 0ull, CH, ot, sNC, CH,
                                                  out, sNC, NPIX, p_b, 1.0f, x, CH);
}

// round 5
// speedup vs baseline: 5.3230x; 1.0606x over previous
#include <cuda_runtime.h>
#include <cuda_bf16.h>
#include <cstdint>

#define BATCH 8
#define CH    512
#define NPIX  4096
#define EPS   1e-6f

// ---------------------------------------------------------------------------
// Scratch (__device__ globals: allocation-free per harness rules)
// ---------------------------------------------------------------------------
__device__ __nv_bfloat16 g_ht[BATCH * NPIX * CH];   // h transposed [b][n][c]
__device__ __nv_bfloat16 g_qt[BATCH * NPIX * CH];   // q_t [b][n][d]
__device__ __nv_bfloat16 g_kt[BATCH * NPIX * CH];   // k_t [b][n][d]
__device__ __nv_bfloat16 g_v [BATCH * CH * NPIX];   // v   [b][d][n]
__device__ __nv_bfloat16 g_ot[BATCH * NPIX * CH];   // o_t [b][n][c]
__device__ __nv_bfloat16 g_S [134217728];           // [b][i][j] exp(logits)
__device__ float         g_rowsum[BATCH * NPIX];    // softmax denominators
__device__ __nv_bfloat16 g_wq[CH * CH], g_wk[CH * CH], g_wv[CH * CH], g_wp[CH * CH];

// ---------------------------------------------------------------------------
// PTX helpers (base-arch features only: PTX target is sm_103 w/o 'a' suffix)
// ---------------------------------------------------------------------------
__device__ __forceinline__ uint32_t smem_u32(const void* p) {
    uint32_t a;
    asm("{ .reg .u64 t; cvta.to.shared.u64 t, %1; cvt.u32.u64 %0, t; }"
        : "=r"(a) : "l"(p));
    return a;
}
__device__ __forceinline__ void cp_async16(uint32_t saddr, const void* gptr) {
    asm volatile("cp.async.cg.shared.global [%0], [%1], 16;\n"
                 :: "r"(saddr), "l"(gptr));
}
#define CP_COMMIT() asm volatile("cp.async.commit_group;\n" ::: "memory")
#define CP_WAIT(N)  asm volatile("cp.async.wait_group %0;\n" :: "n"(N) : "memory")

__device__ __forceinline__ void ldsm4(uint32_t* r, uint32_t addr) {
    asm volatile("ldmatrix.sync.aligned.m8n8.x4.shared.b16 {%0,%1,%2,%3}, [%4];"
                 : "=r"(r[0]), "=r"(r[1]), "=r"(r[2]), "=r"(r[3]) : "r"(addr));
}
__device__ __forceinline__ void mma16816(float* c, const uint32_t* a,
                                         uint32_t b0, uint32_t b1) {
    asm volatile("mma.sync.aligned.m16n8k16.row.col.f32.bf16.bf16.f32 "
                 "{%0,%1,%2,%3}, {%4,%5,%6,%7}, {%8,%9}, {%0,%1,%2,%3};"
                 : "+f"(c[0]), "+f"(c[1]), "+f"(c[2]), "+f"(c[3])
                 : "r"(a[0]), "r"(a[1]), "r"(a[2]), "r"(a[3]), "r"(b0), "r"(b1));
}

// ---------------------------------------------------------------------------
// GroupNorm -> bf16, TRANSPOSED output g_ht[b][n][c]
// ---------------------------------------------------------------------------
__global__ __launch_bounds__(1024) void gn_kernel(const float* __restrict__ x,
                                                  const float* __restrict__ w,
                                                  const float* __restrict__ bgn) {
    int bg = blockIdx.x;                       // b*32 + g
    size_t base = (size_t)bg * (16 * NPIX);
    const float4* x4 = (const float4*)(x + base);
    int tid = threadIdx.x;

    float s = 0.f, ss = 0.f;
    #pragma unroll
    for (int t = 0; t < 16; t++) {
        float4 v = x4[tid + t * 1024];
        s  += v.x + v.y + v.z + v.w;
        ss += v.x * v.x + v.y * v.y + v.z * v.z + v.w * v.w;
    }
    __shared__ float rs[32], rss[32];
    __shared__ float sc_s[16], off_s[16];
    #pragma unroll
    for (int o = 16; o; o >>= 1) {
        s  += __shfl_xor_sync(0xffffffffu, s, o);
        ss += __shfl_xor_sync(0xffffffffu, ss, o);
    }
    if ((tid & 31) == 0) { rs[tid >> 5] = s; rss[tid >> 5] = ss; }
    __syncthreads();
    if (tid < 32) {
        s = rs[tid]; ss = rss[tid];
        #pragma unroll
        for (int o = 16; o; o >>= 1) {
            s  += __shfl_xor_sync(0xffffffffu, s, o);
            ss += __shfl_xor_sync(0xffffffffu, ss, o);
        }
        if (tid == 0) {
            float mean = s * (1.f / 65536.f);
            float var  = ss * (1.f / 65536.f) - mean * mean;
            rs[0] = mean; rss[0] = rsqrtf(var + EPS);
        }
    }
    __syncthreads();
    int b = bg >> 5, g = bg & 31, c0 = g * 16;
    if (tid < 16) {
        float mean = rs[0], inv = rss[0];
        float scv = w[c0 + tid] * inv;
        sc_s[tid]  = scv;
        off_s[tid] = bgn[c0 + tid] - mean * scv;
    }
    __syncthreads();

    #pragma unroll
    for (int nb = 0; nb < 4; nb++) {
        int n = nb * 1024 + tid;
        __nv_bfloat16 hv[16];
        #pragma unroll
        for (int cc = 0; cc < 16; cc++) {
            float xv = x[base + (size_t)cc * NPIX + n];
            hv[cc] = __float2bfloat16(xv * sc_s[cc] + off_s[cc]);
        }
        uint4* dst = (uint4*)(g_ht + ((size_t)b * NPIX + n) * CH + c0);
        uint4* src = (uint4*)hv;
        dst[0] = src[0];
        dst[1] = src[1];
    }
}

// ---------------------------------------------------------------------------
// Convert 4 weight matrices fp32 -> bf16; also zero g_rowsum.
// ---------------------------------------------------------------------------
__global__ __launch_bounds__(256) void wconv_kernel(const float* __restrict__ q,
                                                    const float* __restrict__ k,
                                                    const float* __restrict__ v,
                                                    const float* __restrict__ p) {
    int i4 = blockIdx.x * 256 + threadIdx.x;   // float4 units
    if (i4 < BATCH * NPIX) g_rowsum[i4] = 0.f;
    const float* src = (i4 < 65536) ? q : (i4 < 131072) ? k : (i4 < 196608) ? v : p;
    __nv_bfloat16* dst = (i4 < 65536) ? g_wq : (i4 < 131072) ? g_wk : (i4 < 196608) ? g_wv : g_wp;
    int off = i4 & 65535;
    float4 vv = ((const float4*)src)[off];
    __nv_bfloat162 lo = __floats2bfloat162_rn(vv.x, vv.y);
    __nv_bfloat162 hi = __floats2bfloat162_rn(vv.z, vv.w);
    uint2 u; u.x = *(uint32_t*)&lo; u.y = *(uint32_t*)&hi;
    ((uint2*)dst)[off] = u;
}

// ---------------------------------------------------------------------------
// mma.sync bf16 GEMM: D[M x N] = sum_k A[m,k]*B[n,k], both K-major bf16.
// CTA tile 128x128, BK=64, 3-stage cp.async pipeline, swizzled smem,
// warp tile 64x32 (8 warps as 2x4), m16n8k16 fragments.
// EPI: 0 = bf16 (acc + bias[col]) * scale
//      1 = bf16  acc + bias[row]
//      3 = fp32  x + acc + bias[row]            (residual output)
//      4 = bf16  exp(acc), accumulate row sums into g_rowsum (softmax numer)
//      5 = bf16  acc * (1/g_rowsum[row])        (softmax denom applied)
// ---------------------------------------------------------------------------
template<int EPI>
__global__ void __launch_bounds__(256, 2) tc_gemm(
    const __nv_bfloat16* __restrict__ A, unsigned long long sA, int ldA,
    const __nv_bfloat16* __restrict__ B, unsigned long long sB, int ldB,
    void* __restrict__ C, unsigned long long sC, int ldC,
    const float* __restrict__ bias, float scale,
    const float* __restrict__ Xres, int K)
{
    extern __shared__ char dsm[];
    uint32_t sb = smem_u32(dsm);
    const uint32_t STG = 32768;                  // per-stage: A 16KB + B 16KB
    int tid = threadIdx.x, wid = tid >> 5, lane = tid & 31;
    int wm = wid >> 2, wn = wid & 3;

    const __nv_bfloat16* Ab = A + (size_t)blockIdx.z * sA + (size_t)blockIdx.y * 128 * ldA;
    const __nv_bfloat16* Bb = B + (size_t)blockIdx.z * sB + (size_t)blockIdx.x * 128 * ldB;

    // ldmatrix lane address components (swizzle: byte = row*128 + (kb ^ ((row&7)<<4)))
    int a_row = wm * 64 + (lane & 7) + ((lane >> 3) & 1) * 8;
    int a_kl  = (lane >> 4) * 16;
    uint32_t xr_a = (uint32_t)((a_row & 7) << 4);
    uint32_t a_off[4];
    #pragma unroll
    for (int i = 0; i < 4; i++) a_off[i] = (uint32_t)((a_row + i * 16) * 128);

    int b_row = wn * 32 + (lane & 7) + ((lane >> 4) << 3);
    int b_kl  = ((lane >> 3) & 1) * 16;
    uint32_t xr_b = (uint32_t)((b_row & 7) << 4);
    uint32_t b_off[2];
    #pragma unroll
    for (int p = 0; p < 2; p++) b_off[p] = (uint32_t)((b_row + p * 16) * 128);

    float acc[4][4][4];
    #pragma unroll
    for (int i = 0; i < 4; i++)
        #pragma unroll
        for (int j = 0; j < 4; j++)
            #pragma unroll
            for (int e = 0; e < 4; e++) acc[i][j][e] = 0.f;

    int nch = K >> 6;

    auto load_stage = [&](int stg, int c) {
        uint32_t as = sb + (uint32_t)stg * STG;
        uint32_t bs = as + 16384;
        const __nv_bfloat16* ga = Ab + c * 64;
        const __nv_bfloat16* gb = Bb + c * 64;
        #pragma unroll
        for (int t = 0; t < 4; t++) {
            int sidx = t * 256 + tid;
            int m = sidx >> 3, cc = sidx & 7;
            uint32_t off = (uint32_t)(m * 128) + ((uint32_t)(cc * 16) ^ ((uint32_t)(m & 7) << 4));
            cp_async16(as + off, ga + (size_t)m * ldA + cc * 8);
            cp_async16(bs + off, gb + (size_t)m * ldB + cc * 8);
        }
    };

    if (0 < nch) { load_stage(0, 0); CP_COMMIT(); }
    if (1 < nch) { load_stage(1, 1); CP_COMMIT(); }

    for (int c = 0; c < nch; c++) {
        if (c + 2 < nch) { load_stage((c + 2) % 3, c + 2); CP_COMMIT(); }
        int remaining = nch - 1 - c;
        if (remaining >= 2)      { CP_WAIT(2); }
        else if (remaining == 1) { CP_WAIT(1); }
        else                     { CP_WAIT(0); }
        __syncthreads();

        uint32_t As = sb + (uint32_t)(c % 3) * STG;
        uint32_t Bs = As + 16384;
        #pragma unroll
        for (int k0 = 0; k0 < 64; k0 += 16) {
            uint32_t a[4][4], b[2][4];
            #pragma unroll
            for (int i = 0; i < 4; i++)
                ldsm4(a[i], As + a_off[i] + ((uint32_t)(k0 * 2 + a_kl) ^ xr_a));
            #pragma unroll
            for (int p = 0; p < 2; p++)
                ldsm4(b[p], Bs + b_off[p] + ((uint32_t)(k0 * 2 + b_kl) ^ xr_b));
            #pragma unroll
            for (int i = 0; i < 4; i++)
                #pragma unroll
                for (int j = 0; j < 4; j++)
                    mma16816(acc[i][j], a[i], b[j >> 1][(j & 1) * 2], b[j >> 1][(j & 1) * 2 + 1]);
        }
        __syncthreads();
    }

    // ---- epilogue: direct global stores ----
    int r0 = lane >> 2, cq = (lane & 3) * 2;
    #pragma unroll
    for (int i = 0; i < 4; i++) {
        int rowg0 = blockIdx.y * 128 + wm * 64 + i * 16 + r0;
        float inv_lo = 0.f, inv_hi = 0.f;
        if (EPI == 5) {
            const float* rsum = g_rowsum + (size_t)blockIdx.z * NPIX;
            inv_lo = 1.f / rsum[rowg0];
            inv_hi = 1.f / rsum[rowg0 + 8];
        }
        float p_lo = 0.f, p_hi = 0.f;
        #pragma unroll
        for (int j = 0; j < 4; j++) {
            int colg = blockIdx.x * 128 + wn * 32 + j * 8 + cq;
            float v0 = acc[i][j][0], v1 = acc[i][j][1];
            float v2 = acc[i][j][2], v3 = acc[i][j][3];
            if (EPI == 0) {
                float b0 = bias[colg], b1 = bias[colg + 1];
                v0 = (v0 + b0) * scale; v1 = (v1 + b1) * scale;
                v2 = (v2 + b0) * scale; v3 = (v3 + b1) * scale;
            } else if (EPI == 1 || EPI == 3) {
                float bu = bias[rowg0], bl = bias[rowg0 + 8];
                v0 += bu; v1 += bu; v2 += bl; v3 += bl;
            } else if (EPI == 4) {
                v0 = __expf(v0); v1 = __expf(v1);
                v2 = __expf(v2); v3 = __expf(v3);
                p_lo += v0 + v1; p_hi += v2 + v3;
            } else if (EPI == 5) {
                v0 *= inv_lo; v1 *= inv_lo;
                v2 *= inv_hi; v3 *= inv_hi;
            }
            size_t o0 = (size_t)blockIdx.z * sC + (size_t)rowg0 * ldC + colg;
            size_t o1 = o0 + (size_t)8 * ldC;
            if (EPI == 3) {
                const float* Xr0 = Xres + o0;
                const float* Xr1 = Xres + o1;
                float2 f0; f0.x = Xr0[0] + v0; f0.y = Xr0[1] + v1;
                float2 f1; f1.x = Xr1[0] + v2; f1.y = Xr1[1] + v3;
                *(float2*)((float*)C + o0) = f0;
                *(float2*)((float*)C + o1) = f1;
            } else {
                __nv_bfloat162 q0 = __floats2bfloat162_rn(v0, v1);
                __nv_bfloat162 q1 = __floats2bfloat162_rn(v2, v3);
                *(__nv_bfloat162*)((__nv_bfloat16*)C + o0) = q0;
                *(__nv_bfloat162*)((__nv_bfloat16*)C + o1) = q1;
            }
        }
        if (EPI == 4) {
            // reduce across the 4 lanes of the quad (same rows, different cols)
            p_lo += __shfl_xor_sync(0xffffffffu, p_lo, 1);
            p_lo += __shfl_xor_sync(0xffffffffu, p_lo, 2);
            p_hi += __shfl_xor_sync(0xffffffffu, p_hi, 1);
            p_hi += __shfl_xor_sync(0xffffffffu, p_hi, 2);
            if ((lane & 3) == 0) {
                float* rsum = g_rowsum + (size_t)blockIdx.z * NPIX;
                atomicAdd(rsum + rowg0, p_lo);
                atomicAdd(rsum + rowg0 + 8, p_hi);
            }
        }
    }
}

// ---------------------------------------------------------------------------
extern "C" void kernel_launch(void* const* d_in, const int* in_sizes, int n_in,
                              void* d_out, int out_size) {
    (void)in_sizes; (void)n_in; (void)out_size;
    const float* x    = (const float*)d_in[0];
    const float* gn_w = (const float*)d_in[1];
    const float* gn_b = (const float*)d_in[2];
    const float* q_w  = (const float*)d_in[3];
    const float* q_b  = (const float*)d_in[4];
    const float* k_w  = (const float*)d_in[5];
    const float* k_b  = (const float*)d_in[6];
    const float* v_w  = (const float*)d_in[7];
    const float* v_b  = (const float*)d_in[8];
    const float* p_w  = (const float*)d_in[9];
    const float* p_b  = (const float*)d_in[10];
    float* out = (float*)d_out;

    const float qscale = 0.044194173824159216f;  // 512^-0.5
    const int SMEM = 98304;                      // 3 stages x 32KB
    static bool attr_done = false;
    if (!attr_done) {
        cudaFuncSetAttribute(tc_gemm<0>, cudaFuncAttributeMaxDynamicSharedMemorySize, SMEM);
        cudaFuncSetAttribute(tc_gemm<1>, cudaFuncAttributeMaxDynamicSharedMemorySize, SMEM);
        cudaFuncSetAttribute(tc_gemm<3>, cudaFuncAttributeMaxDynamicSharedMemorySize, SMEM);
        cudaFuncSetAttribute(tc_gemm<4>, cudaFuncAttributeMaxDynamicSharedMemorySize, SMEM);
        cudaFuncSetAttribute(tc_gemm<5>, cudaFuncAttributeMaxDynamicSharedMemorySize, SMEM);
        attr_done = true;
    }

    __nv_bfloat16 *ht, *qt, *kt, *vv, *ot, *Sp, *wq, *wk, *wv, *wp;
    cudaGetSymbolAddress((void**)&ht, g_ht);
    cudaGetSymbolAddress((void**)&qt, g_qt);
    cudaGetSymbolAddress((void**)&kt, g_kt);
    cudaGetSymbolAddress((void**)&vv, g_v);
    cudaGetSymbolAddress((void**)&ot, g_ot);
    cudaGetSymbolAddress((void**)&Sp, g_S);
    cudaGetSymbolAddress((void**)&wq, g_wq);
    cudaGetSymbolAddress((void**)&wk, g_wk);
    cudaGetSymbolAddress((void**)&wv, g_wv);
    cudaGetSymbolAddress((void**)&wp, g_wp);

    const unsigned long long sNC = (unsigned long long)NPIX * CH;    // 2097152
    const unsigned long long sNN = (unsigned long long)NPIX * NPIX;  // 16777216

    gn_kernel<<<BATCH * 32, 1024>>>(x, gn_w, gn_b);
    wconv_kernel<<<1024, 256>>>(q_w, k_w, v_w, p_w);

    // q_t[n][d] = (h_t . Wq^T + qb) * qscale : M=4096, N=512, K=512
    tc_gemm<0><<<dim3(4, 32, BATCH), 256, SMEM>>>(ht, sNC, CH, wq, 0ull, CH,
                                                  qt, sNC, CH, q_b, qscale, nullptr, CH);
    tc_gemm<0><<<dim3(4, 32, BATCH), 256, SMEM>>>(ht, sNC, CH, wk, 0ull, CH,
                                                  kt, sNC, CH, k_b, 1.0f, nullptr, CH);
    // v[d][n] = Wv . h_t^T + vb : M=512, N=4096, K=512
    tc_gemm<1><<<dim3(32, 4, BATCH), 256, SMEM>>>(wv, 0ull, CH, ht, sNC, CH,
                                                  vv, sNC, NPIX, v_b, 1.0f, nullptr, CH);
    // expS[i][j] = exp(q_t . k_t^T), rowsum accumulated : M=4096, N=4096, K=512
    tc_gemm<4><<<dim3(32, 32, BATCH), 256, SMEM>>>(qt, sNC, CH, kt, sNC, CH,
                                                   Sp, sNN, NPIX, nullptr, 1.0f, nullptr, CH);
    // o_t[i][c] = (expS . v^T) / rowsum[i] : M=4096, N=512, K=4096
    tc_gemm<5><<<dim3(4, 32, BATCH), 256, SMEM>>>(Sp, sNN, NPIX, vv, sNC, NPIX,
                                                  ot, sNC, CH, nullptr, 1.0f, nullptr, NPIX);
    // out[d][n] = x + Wp . o_t^T + pb : M=512, N=4096, K=512 (fp32 out)
    tc_gemm<3><<<dim3(32, 4, BATCH), 256, SMEM>>>(wp, 0ull, CH, ot, sNC, CH,
                                                  out, sNC, NPIX, p_b, 1.0f, x, CH);
}